// round 16
// baseline (speedup 1.0000x reference)
#include <cuda_runtime.h>
#include <cuda_fp16.h>
#include <cstdint>

// x [4,256,256,128], DIM=HID=128, R = 262144 rows.
constexpr int LDAH = 136;  // fp16 activation ld in halves (272B; %128==16 -> CF)
constexpr int WLDH = 272;  // fp16 k-pair tiles: halves per kp-row (544B; %128==32 -> CF)

constexpr int SMEM_PRE  = (64 * LDAH + 2 * 64 * WLDH) * 2;   // 87,040 -> 2 CTAs/SM
constexpr int SMEM_MIX  = 4 * 32 * WLDH * 2;                 // 69,632
constexpr int SMEM_POST = (64 * LDAH + 64 * WLDH) * 2;       // 52,224

// Scratch (device globals). All intermediates fp16 halves.
__device__ float g_leftT [33554432];  // halves: [b][d][k/2][j][2]
__device__ float g_rightT[33554432];  // halves: [b][d][k/2][i][2]
__device__ float g_ogate [16777216];  // halves: [r][d]
__device__ float g_mixT  [16777216];  // halves: [b][d][i][j]

__device__ __forceinline__ uint32_t h2u(__half2 h) {
    return *reinterpret_cast<uint32_t*>(&h);
}
__device__ __forceinline__ float sigm(float x) { return 1.0f / (1.0f + __expf(-x)); }

__device__ __forceinline__ void mma16(float c[4], const uint32_t a[4], uint32_t b0, uint32_t b1) {
    asm volatile(
        "mma.sync.aligned.m16n8k16.row.col.f32.f16.f16.f32 "
        "{%0,%1,%2,%3},{%4,%5,%6,%7},{%8,%9},{%0,%1,%2,%3};\n"
        : "+f"(c[0]), "+f"(c[1]), "+f"(c[2]), "+f"(c[3])
        : "r"(a[0]), "r"(a[1]), "r"(a[2]), "r"(a[3]), "r"(b0), "r"(b1));
}

template <int NT>
__device__ __forceinline__ void zacc2(float (&a)[2][NT][4]) {
#pragma unroll
    for (int i = 0; i < 2; i++)
#pragma unroll
        for (int j = 0; j < NT; j++)
#pragma unroll
            for (int k = 0; k < 4; k++) a[i][j][k] = 0.f;
}
template <int NT>
__device__ __forceinline__ void zacc1(float (&a)[NT][4]) {
#pragma unroll
    for (int j = 0; j < NT; j++)
#pragma unroll
        for (int k = 0; k < 4; k++) a[j][k] = 0.f;
}

// ---- k_pre fp16 dual GEMM, M-tile 16: A row-major fp16 (ld=LDAH), B [kp][n][2] ----
template <int NT>
__device__ __forceinline__ void gemm_dual_h16(const __half* __restrict__ sa,
                                              const __half* __restrict__ wA,
                                              const __half* __restrict__ wB,
                                              float (&acc1)[NT][4], float (&acc2)[NT][4],
                                              int m_base, int n_base, int g, int tg) {
#pragma unroll
    for (int ks = 0; ks < 8; ++ks) {       // K=16 per step
        uint32_t a[4];
        const __half* p0 = sa + (m_base + g) * LDAH + ks * 16 + tg * 2;
        const __half* p1 = sa + (m_base + 8 + g) * LDAH + ks * 16 + tg * 2;
        a[0] = *reinterpret_cast<const uint32_t*>(p0);
        a[1] = *reinterpret_cast<const uint32_t*>(p1);
        a[2] = *reinterpret_cast<const uint32_t*>(p0 + 8);
        a[3] = *reinterpret_cast<const uint32_t*>(p1 + 8);
#pragma unroll
        for (int nt = 0; nt < NT; ++nt) {
            int cn = n_base + nt * 8 + g;
            uint32_t b00 = *reinterpret_cast<const uint32_t*>(wA + (ks * 8 + tg) * WLDH + cn * 2);
            uint32_t b01 = *reinterpret_cast<const uint32_t*>(wA + (ks * 8 + 4 + tg) * WLDH + cn * 2);
            uint32_t b10 = *reinterpret_cast<const uint32_t*>(wB + (ks * 8 + tg) * WLDH + cn * 2);
            uint32_t b11 = *reinterpret_cast<const uint32_t*>(wB + (ks * 8 + 4 + tg) * WLDH + cn * 2);
            mma16(acc1[nt], a, b00, b01);
            mma16(acc2[nt], a, b10, b11);
        }
    }
}

template <int NT>
__device__ __forceinline__ void gemm_single_h16(const __half* __restrict__ sa,
                                                const __half* __restrict__ wA,
                                                float (&acc)[NT][4],
                                                int m_base, int n_base, int g, int tg) {
#pragma unroll
    for (int ks = 0; ks < 8; ++ks) {
        uint32_t a[4];
        const __half* p0 = sa + (m_base + g) * LDAH + ks * 16 + tg * 2;
        const __half* p1 = sa + (m_base + 8 + g) * LDAH + ks * 16 + tg * 2;
        a[0] = *reinterpret_cast<const uint32_t*>(p0);
        a[1] = *reinterpret_cast<const uint32_t*>(p1);
        a[2] = *reinterpret_cast<const uint32_t*>(p0 + 8);
        a[3] = *reinterpret_cast<const uint32_t*>(p1 + 8);
#pragma unroll
        for (int nt = 0; nt < NT; ++nt) {
            int cn = n_base + nt * 8 + g;
            uint32_t b0 = *reinterpret_cast<const uint32_t*>(wA + (ks * 8 + tg) * WLDH + cn * 2);
            uint32_t b1 = *reinterpret_cast<const uint32_t*>(wA + (ks * 8 + 4 + tg) * WLDH + cn * 2);
            mma16(acc[nt], a, b0, b1);
        }
    }
}

// ---- k_post fp16 GEMM (M-tile 32, unchanged from R15) ----
template <int NT>
__device__ __forceinline__ void gemm_single_h(const __half* __restrict__ sa,
                                              const __half* __restrict__ wA,
                                              float (&acc)[2][NT][4],
                                              int m_base, int n_base, int g, int tg) {
#pragma unroll
    for (int ks = 0; ks < 8; ++ks) {
        uint32_t a[2][4];
#pragma unroll
        for (int mt = 0; mt < 2; ++mt) {
            int r = m_base + mt * 16;
            const __half* p0 = sa + (r + g) * LDAH + ks * 16 + tg * 2;
            const __half* p1 = sa + (r + 8 + g) * LDAH + ks * 16 + tg * 2;
            a[mt][0] = *reinterpret_cast<const uint32_t*>(p0);
            a[mt][1] = *reinterpret_cast<const uint32_t*>(p1);
            a[mt][2] = *reinterpret_cast<const uint32_t*>(p0 + 8);
            a[mt][3] = *reinterpret_cast<const uint32_t*>(p1 + 8);
        }
#pragma unroll
        for (int nt = 0; nt < NT; ++nt) {
            int cn = n_base + nt * 8 + g;
            uint32_t b0 = *reinterpret_cast<const uint32_t*>(wA + (ks * 8 + tg) * WLDH + cn * 2);
            uint32_t b1 = *reinterpret_cast<const uint32_t*>(wA + (ks * 8 + 4 + tg) * WLDH + cn * 2);
            mma16(acc[0][nt], a[0], b0, b1);
            mma16(acc[1][nt], a[1], b0, b1);
        }
    }
}

// ---- k_mix fp16 GEMM over one K=64 chunk ----
__device__ __forceinline__ void gemm_h64(const __half* __restrict__ sa,
                                         const __half* __restrict__ sb,
                                         float (&acc)[2][8][4],
                                         int m_base, int n_base, int g, int tg) {
#pragma unroll
    for (int ks = 0; ks < 4; ++ks) {
        const int kp0 = ks * 8;
        uint32_t a[2][4];
#pragma unroll
        for (int mt = 0; mt < 2; ++mt) {
            int ib = m_base + mt * 16;
            a[mt][0] = *reinterpret_cast<const uint32_t*>(sa + (kp0 + tg) * WLDH + (ib + g) * 2);
            a[mt][1] = *reinterpret_cast<const uint32_t*>(sa + (kp0 + tg) * WLDH + (ib + 8 + g) * 2);
            a[mt][2] = *reinterpret_cast<const uint32_t*>(sa + (kp0 + tg + 4) * WLDH + (ib + g) * 2);
            a[mt][3] = *reinterpret_cast<const uint32_t*>(sa + (kp0 + tg + 4) * WLDH + (ib + 8 + g) * 2);
        }
#pragma unroll
        for (int nt = 0; nt < 8; ++nt) {
            int cn = n_base + nt * 8 + g;
            uint32_t b0 = *reinterpret_cast<const uint32_t*>(sb + (kp0 + tg) * WLDH + cn * 2);
            uint32_t b1 = *reinterpret_cast<const uint32_t*>(sb + (kp0 + tg + 4) * WLDH + cn * 2);
            mma16(acc[0][nt], a[0], b0, b1);
            mma16(acc[1][nt], a[1], b0, b1);
        }
    }
}

// fp16 weight load: gmem W[k][n] -> smem [kp][n][2] halves
template <int NTHR>
__device__ __forceinline__ void loadW_h(__half* __restrict__ sw, const float* __restrict__ W, int tid) {
    for (int idx = tid; idx < 2048; idx += NTHR) {
        int kp = idx >> 5, nq = idx & 31;
        float4 v0 = __ldg(reinterpret_cast<const float4*>(W + (kp * 2) * 128) + nq);
        float4 v1 = __ldg(reinterpret_cast<const float4*>(W + (kp * 2 + 1) * 128) + nq);
        uint4 o;
        o.x = h2u(__floats2half2_rn(v0.x, v1.x));
        o.y = h2u(__floats2half2_rn(v0.y, v1.y));
        o.z = h2u(__floats2half2_rn(v0.z, v1.z));
        o.w = h2u(__floats2half2_rn(v0.w, v1.w));
        *reinterpret_cast<uint4*>(sw + kp * WLDH + nq * 8) = o;
    }
}

// combine (M-tile 16) + direct fp16 writeout to interleaved [d][k/2][j][2] halves
template <int NT>
__device__ __forceinline__ void combine_direct_h16(__half* __restrict__ dstT, int krow, int j0,
                                                   const float (&acc1)[NT][4], const float (&acc2)[NT][4],
                                                   const float* __restrict__ blin, const float* __restrict__ bgat,
                                                   int m_base, int n_base, int g, int tg) {
    const size_t rowoff = (size_t)(krow >> 1) * 512 + (size_t)(krow & 1);
    int j = j0 + m_base + g;
#pragma unroll
    for (int nt = 0; nt < NT; ++nt) {
        int d0 = n_base + nt * 8 + tg * 2;
        float bl0 = blin[d0], bl1 = blin[d0 + 1];
        float bg0 = bgat[d0], bg1 = bgat[d0 + 1];
        __half v00 = __float2half_rn((acc1[nt][0] + bl0) * sigm(acc2[nt][0] + bg0));
        __half v01 = __float2half_rn((acc1[nt][1] + bl1) * sigm(acc2[nt][1] + bg1));
        __half v10 = __float2half_rn((acc1[nt][2] + bl0) * sigm(acc2[nt][2] + bg0));
        __half v11 = __float2half_rn((acc1[nt][3] + bl1) * sigm(acc2[nt][3] + bg1));
        __half* p0 = dstT + (((size_t)d0) << 16) + rowoff + (size_t)j * 2;
        __half* p1 = dstT + (((size_t)(d0 + 1)) << 16) + rowoff + (size_t)j * 2;
        p0[0]  = v00;  p1[0]  = v01;
        p0[16] = v10;  p1[16] = v11;   // j+8 -> +16 halves
    }
}

// -- Kernel 1: LN + 5 projections, 64-row tiles, 512 thr, 2 CTAs/SM --
__global__ void __launch_bounds__(512, 2) k_pre(
    const float* __restrict__ x, const float* __restrict__ ng, const float* __restrict__ nb,
    const float* __restrict__ wL, const float* __restrict__ bL,
    const float* __restrict__ wR, const float* __restrict__ bR,
    const float* __restrict__ wLG, const float* __restrict__ bLG,
    const float* __restrict__ wRG, const float* __restrict__ bRG,
    const float* __restrict__ wOG, const float* __restrict__ bOG) {
    extern __shared__ __half smemh[];
    __half* sx = smemh;                      // 64 x LDAH halves
    __half* w0 = smemh + 64 * LDAH;          // 64 x WLDH halves
    __half* w1 = w0 + 64 * WLDH;

    const int tid = threadIdx.x, lane = tid & 31, warp = tid >> 5;
    const int g = lane >> 2, tg = lane & 3;
    const int r0 = blockIdx.x << 6;
    const int b = r0 >> 16, krow = (r0 >> 8) & 255, j0 = r0 & 255;
    const int m_base = (warp >> 2) * 16, n_base = (warp & 3) * 32;
    const size_t plane = ((size_t)b * 128) << 16;   // halves

    // Phase A: load wL/wLG + LN (64 rows, 4 rows/warp)
    loadW_h<512>(w0, wL, tid);
    loadW_h<512>(w1, wLG, tid);
    {
        float4 g4 = reinterpret_cast<const float4*>(ng)[lane];
        float4 b4 = reinterpret_cast<const float4*>(nb)[lane];
        for (int row = warp * 4; row < warp * 4 + 4; ++row) {
            float4 v = reinterpret_cast<const float4*>(x + ((size_t)(r0 + row)) * 128)[lane];
            float s = v.x + v.y + v.z + v.w;
            float q = fmaf(v.x, v.x, fmaf(v.y, v.y, fmaf(v.z, v.z, v.w * v.w)));
#pragma unroll
            for (int o = 16; o; o >>= 1) {
                s += __shfl_xor_sync(0xffffffffu, s, o);
                q += __shfl_xor_sync(0xffffffffu, q, o);
            }
            float mu = s * 0.0078125f;
            float rs = rsqrtf(fmaf(-mu, mu, q * 0.0078125f) + 1e-5f);
            __half2 h0 = __floats2half2_rn(fmaf((v.x - mu) * rs, g4.x, b4.x),
                                           fmaf((v.y - mu) * rs, g4.y, b4.y));
            __half2 h1 = __floats2half2_rn(fmaf((v.z - mu) * rs, g4.z, b4.z),
                                           fmaf((v.w - mu) * rs, g4.w, b4.w));
            uint2 o2 = {h2u(h0), h2u(h1)};
            *reinterpret_cast<uint2*>(sx + row * LDAH + lane * 4) = o2;
        }
    }
    __syncthreads();

    float acc1[4][4], acc2[4][4];

    // Phase B: left pair + writeout
    zacc1(acc1); zacc1(acc2);
    gemm_dual_h16<4>(sx, w0, w1, acc1, acc2, m_base, n_base, g, tg);
    combine_direct_h16<4>(reinterpret_cast<__half*>(g_leftT) + plane, krow, j0,
                          acc1, acc2, bL, bLG, m_base, n_base, g, tg);
    __syncthreads();

    // Phase C: load wR/wRG
    loadW_h<512>(w0, wR, tid);
    loadW_h<512>(w1, wRG, tid);
    __syncthreads();

    // Phase D: right pair + writeout
    zacc1(acc1); zacc1(acc2);
    gemm_dual_h16<4>(sx, w0, w1, acc1, acc2, m_base, n_base, g, tg);
    combine_direct_h16<4>(reinterpret_cast<__half*>(g_rightT) + plane, krow, j0,
                          acc1, acc2, bR, bRG, m_base, n_base, g, tg);
    __syncthreads();

    // Phase E: load wOG
    loadW_h<512>(w0, wOG, tid);
    __syncthreads();

    // Phase F: ogate gemm + fp16 row-major epilogue
    zacc1(acc2);
    gemm_single_h16<4>(sx, w0, acc2, m_base, n_base, g, tg);
    __half* og = reinterpret_cast<__half*>(g_ogate);
    {
        int row = m_base + g;
#pragma unroll
        for (int nt = 0; nt < 4; ++nt) {
            int cn = n_base + nt * 8 + tg * 2;
            float bg0 = bOG[cn], bg1 = bOG[cn + 1];
            uint32_t p0 = h2u(__floats2half2_rn(sigm(acc2[nt][0] + bg0), sigm(acc2[nt][1] + bg1)));
            uint32_t p1 = h2u(__floats2half2_rn(sigm(acc2[nt][2] + bg0), sigm(acc2[nt][3] + bg1)));
            *reinterpret_cast<uint32_t*>(og + ((size_t)(r0 + row)) * 128 + cn) = p0;
            *reinterpret_cast<uint32_t*>(og + ((size_t)(r0 + row + 8)) * 128 + cn) = p1;
        }
    }
}

// -------------------- Kernel 2: fp16 triangle einsum (2-stage, K-chunk 64) ---------------
__device__ __forceinline__ void cp_tile_h(__half* __restrict__ sdst, const __half* __restrict__ gsrc, int tid) {
#pragma unroll
    for (int m = 0; m < 4; ++m) {
        int i = tid + m * 256;
        int row = i >> 5, seg = (i & 31) * 8;
        uint32_t dst = (uint32_t)__cvta_generic_to_shared(sdst + row * WLDH + seg);
        asm volatile("cp.async.ca.shared.global [%0], [%1], 16;\n"
                     :: "r"(dst), "l"(gsrc + row * 512 + seg));
    }
}
#define CP_COMMIT asm volatile("cp.async.commit_group;\n")

__global__ void __launch_bounds__(256, 2) k_mix() {
    extern __shared__ __half smemh[];
    __half* sA[2] = {smemh, smemh + 32 * WLDH};
    __half* sB[2] = {smemh + 2 * 32 * WLDH, smemh + 3 * 32 * WLDH};

    const int tid = threadIdx.x, lane = tid & 31, warp = tid >> 5;
    const int g = lane >> 2, tg = lane & 3;
    const int b = blockIdx.z, d = blockIdx.y;
    const int i0 = (blockIdx.x >> 1) << 7, jj0 = (blockIdx.x & 1) << 7;
    const int m_base = (warp >> 1) * 32, n_base = (warp & 1) * 64;

    const size_t plane = ((size_t)(b * 128 + d)) << 16;
    const __half* __restrict__ Rp = reinterpret_cast<const __half*>(g_rightT) + plane + i0 * 2;
    const __half* __restrict__ Lp = reinterpret_cast<const __half*>(g_leftT) + plane + jj0 * 2;
    __half* __restrict__ Mp = reinterpret_cast<__half*>(g_mixT) + plane;

    float acc[2][8][4];
    zacc2(acc);

    cp_tile_h(sA[0], Rp, tid);
    cp_tile_h(sB[0], Lp, tid);
    CP_COMMIT;

#pragma unroll 1
    for (int k = 0; k < 4; ++k) {
        if (k < 3) {
            cp_tile_h(sA[(k + 1) & 1], Rp + (size_t)(k + 1) * 16384, tid);
            cp_tile_h(sB[(k + 1) & 1], Lp + (size_t)(k + 1) * 16384, tid);
            CP_COMMIT;
            asm volatile("cp.async.wait_group 1;\n");
        } else {
            asm volatile("cp.async.wait_group 0;\n");
        }
        __syncthreads();
        gemm_h64(sA[k & 1], sB[k & 1], acc, m_base, n_base, g, tg);
        __syncthreads();
    }

#pragma unroll
    for (int mt = 0; mt < 2; ++mt) {
        int row = m_base + mt * 16 + g;
#pragma unroll
        for (int nt = 0; nt < 8; ++nt) {
            int cn = n_base + nt * 8 + tg * 2;
            uint32_t p0 = h2u(__floats2half2_rn(acc[mt][nt][0], acc[mt][nt][1]));
            uint32_t p1 = h2u(__floats2half2_rn(acc[mt][nt][2], acc[mt][nt][3]));
            *reinterpret_cast<uint32_t*>(Mp + (i0 + row) * 256 + jj0 + cn) = p0;
            *reinterpret_cast<uint32_t*>(Mp + (i0 + row + 8) * 256 + jj0 + cn) = p1;
        }
    }
}

// ------- Kernel 3: LN(mixed fp16) * ogate @ w_out + b_out (64-row tiles, fp16 MMA) -------
__global__ void __launch_bounds__(256, 3) k_post(
    const float* __restrict__ ong, const float* __restrict__ onb,
    const float* __restrict__ wO, const float* __restrict__ bO,
    float* __restrict__ out) {
    extern __shared__ __half smemh[];
    __half* sx = smemh;                 // 64 x LDAH halves
    __half* sw = smemh + 64 * LDAH;     // 64 x WLDH halves

    const int tid = threadIdx.x, lane = tid & 31, warp = tid >> 5;
    const int g = lane >> 2, tg = lane & 3;
    const int r0 = blockIdx.x << 6;
    const int b = r0 >> 16, irow = (r0 >> 8) & 255, j0 = r0 & 255;
    const int m_base = (warp >> 2) * 32, n_base = (warp & 3) * 32;

    loadW_h<256>(sw, wO, tid);

    const __half* Mh = reinterpret_cast<const __half*>(g_mixT);
    for (int i = tid; i < 1024; i += 256) {
        int d = i >> 3, sj = i & 7;
        uint4 v = *reinterpret_cast<const uint4*>(
            Mh + (((size_t)(b * 128 + d)) << 16) + irow * 256 + j0 + sj * 8);
        const __half* hv = reinterpret_cast<const __half*>(&v);
#pragma unroll
        for (int u = 0; u < 8; ++u)
            sx[(sj * 8 + u) * LDAH + d] = hv[u];
    }
    __syncthreads();

    float og_[4], ob_[4];
#pragma unroll
    for (int q_ = 0; q_ < 4; q_++) {
        og_[q_] = ong[lane + 32 * q_];
        ob_[q_] = onb[lane + 32 * q_];
    }
    const __half* gh = reinterpret_cast<const __half*>(g_ogate);
    for (int row = warp * 8; row < warp * 8 + 8; ++row) {
        float v[4];
#pragma unroll
        for (int q_ = 0; q_ < 4; q_++) v[q_] = __half2float(sx[row * LDAH + lane + 32 * q_]);
        float s = v[0] + v[1] + v[2] + v[3];
        float q = fmaf(v[0], v[0], fmaf(v[1], v[1], fmaf(v[2], v[2], v[3] * v[3])));
#pragma unroll
        for (int o = 16; o; o >>= 1) {
            s += __shfl_xor_sync(0xffffffffu, s, o);
            q += __shfl_xor_sync(0xffffffffu, q, o);
        }
        float mu = s * 0.0078125f;
        float rs = rsqrtf(fmaf(-mu, mu, q * 0.0078125f) + 1e-5f);
        const __half* gate = gh + ((size_t)(r0 + row)) * 128;
#pragma unroll
        for (int q_ = 0; q_ < 4; q_++) {
            float y = fmaf((v[q_] - mu) * rs, og_[q_], ob_[q_]) * __half2float(gate[lane + 32 * q_]);
            sx[row * LDAH + lane + 32 * q_] = __float2half_rn(y);
        }
    }
    __syncthreads();

    float acc[2][4][4];
    zacc2(acc);
    gemm_single_h<4>(sx, sw, acc, m_base, n_base, g, tg);

#pragma unroll
    for (int mt = 0; mt < 2; ++mt) {
        int row = m_base + mt * 16 + g;
#pragma unroll
        for (int nt = 0; nt < 4; ++nt) {
            int cn = n_base + nt * 8 + tg * 2;
            float b0v = bO[cn], b1v = bO[cn + 1];
            float2 p0 = {acc[mt][nt][0] + b0v, acc[mt][nt][1] + b1v};
            float2 p1 = {acc[mt][nt][2] + b0v, acc[mt][nt][3] + b1v};
            *reinterpret_cast<float2*>(out + ((size_t)(r0 + row)) * 128 + cn) = p0;
            *reinterpret_cast<float2*>(out + ((size_t)(r0 + row + 8)) * 128 + cn) = p1;
        }
    }
}

extern "C" void kernel_launch(void* const* d_in, const int* in_sizes, int n_in,
                              void* d_out, int out_size) {
    const float* x    = (const float*)d_in[0];
    const float* ng   = (const float*)d_in[1];
    const float* nb   = (const float*)d_in[2];
    const float* wL   = (const float*)d_in[3];
    const float* bL   = (const float*)d_in[4];
    const float* wR   = (const float*)d_in[5];
    const float* bR   = (const float*)d_in[6];
    const float* wLG  = (const float*)d_in[7];
    const float* bLG  = (const float*)d_in[8];
    const float* wRG  = (const float*)d_in[9];
    const float* bRG  = (const float*)d_in[10];
    const float* wOG  = (const float*)d_in[11];
    const float* bOG  = (const float*)d_in[12];
    const float* ong  = (const float*)d_in[13];
    const float* onb  = (const float*)d_in[14];
    const float* wO   = (const float*)d_in[15];
    const float* bO   = (const float*)d_in[16];
    float* out = (float*)d_out;

    cudaFuncSetAttribute(k_pre,  cudaFuncAttributeMaxDynamicSharedMemorySize, SMEM_PRE);
    cudaFuncSetAttribute(k_mix,  cudaFuncAttributeMaxDynamicSharedMemorySize, SMEM_MIX);
    cudaFuncSetAttribute(k_post, cudaFuncAttributeMaxDynamicSharedMemorySize, SMEM_POST);

    k_pre<<<4096, 512, SMEM_PRE>>>(x, ng, nb, wL, bL, wR, bR, wLG, bLG, wRG, bRG, wOG, bOG);
    k_mix<<<dim3(4, 128, 4), 256, SMEM_MIX>>>();
    k_post<<<4096, 256, SMEM_POST>>>(ong, onb, wO, bO, out);
}